// round 12
// baseline (speedup 1.0000x reference)
#include <cuda_runtime.h>
#include <cuda_bf16.h>
#include <cstddef>

#define NUM_CLS 19
#define NCH     64
#define HW      (512*512)
#define NBATCH  8
#define NPIX    (NBATCH*HW)          // 2,097,152 pixels
#define CHUNK   4096                 // pixels per block
#define CHUNKS_PER_IMG (HW/CHUNK)    // 64
#define NCHUNKS (NPIX/CHUNK)         // 512 = grid size (fully resident wave)
#define WARPS   16
#define BLOCK   (WARPS*32)           // 512 threads
#define GROUPS  (NCH/WARPS)          // 4 channel passes per block

__device__ float        g_sums[NUM_CLS * NCH];
__device__ float        g_counts[NUM_CLS];
__device__ unsigned int g_ticket;

// ---------------------------------------------------------------------------
// One fused kernel: scatter-sum + class counts + last-block finalize.
// bins[cls][tid] is thread-private -> no atomics, bank-conflict-free
// (bank = tid % 32 independent of cls since 512 % 32 == 0).
// Grid 512 <= 148 SMs * 4 CTAs -> every block resident, single wave.
// ---------------------------------------------------------------------------
__global__ __launch_bounds__(BLOCK, 4) void fused_kernel(
    const float* __restrict__ in, const int* __restrict__ tgt,
    float* __restrict__ out)
{
    __shared__ float bins[NUM_CLS][BLOCK];          // 38,912 B
    __shared__ unsigned char cls[CHUNK];            //  4,096 B
    __shared__ int   cnt[NUM_CLS];
    __shared__ float fcnt[NUM_CLS];
    __shared__ float fnrm[NUM_CLS];
    __shared__ float rbuf[WARPS];
    __shared__ int   sh_last;

    const int tid  = threadIdx.x;
    const int warp = tid >> 5;
    const int lane = tid & 31;
    const int chunk = blockIdx.x;
    const int b   = chunk / CHUNKS_PER_IMG;
    const int hw0 = (chunk % CHUNKS_PER_IMG) * CHUNK;

#pragma unroll
    for (int k = 0; k < NUM_CLS; k++) bins[k][tid] = 0.f;
    if (tid < NUM_CLS) cnt[tid] = 0;
    __syncthreads();

    // Stage labels (int32 -> u8 in smem) and count them (once per pixel).
    {
        const int4* __restrict__ t4 = (const int4*)(tgt + (size_t)b * HW + hw0);
        uchar4* c4 = (uchar4*)cls;
#pragma unroll
        for (int i = tid; i < CHUNK / 4; i += BLOCK) {
            int4 v = t4[i];
            c4[i] = make_uchar4((unsigned char)v.x, (unsigned char)v.y,
                                (unsigned char)v.z, (unsigned char)v.w);
            atomicAdd(&cnt[v.x], 1); atomicAdd(&cnt[v.y], 1);
            atomicAdd(&cnt[v.z], 1); atomicAdd(&cnt[v.w], 1);
        }
    }
    __syncthreads();
    if (tid < NUM_CLS) atomicAdd(&g_counts[tid], (float)cnt[tid]);

    // Stream features: 4 passes, warp = one channel per pass.
    const uchar4* __restrict__ cls4 = (const uchar4*)cls;
    for (int g = 0; g < GROUPS; g++) {
        const int c = g * WARPS + warp;
        const float4* __restrict__ src = (const float4*)(
            in + ((size_t)b * NCH + c) * HW + hw0);
#pragma unroll 4
        for (int i = lane; i < CHUNK / 4; i += 32) {
            float4 x = __ldcs(src + i);
            uchar4 q = cls4[i];
            bins[q.x][tid] += x.x;
            bins[q.y][tid] += x.y;
            bins[q.z][tid] += x.z;
            bins[q.w][tid] += x.w;
        }
        // Flush this channel: warp-reduce each class, re-zero bins.
#pragma unroll
        for (int k = 0; k < NUM_CLS; k++) {
            float v = bins[k][tid];
            bins[k][tid] = 0.f;
#pragma unroll
            for (int o = 16; o > 0; o >>= 1)
                v += __shfl_down_sync(0xffffffffu, v, o);
            if (lane == 0) atomicAdd(&g_sums[k * NCH + c], v);
        }
    }

    // Ticket: last block to arrive does the finalize.
    __threadfence();
    __syncthreads();
    if (tid == 0)
        sh_last = (atomicAdd(&g_ticket, 1u) == (unsigned)(NCHUNKS - 1));
    __syncthreads();
    if (!sh_last) return;

    // ---------------- finalize (last block only) ----------------
    __threadfence();
    float* cen = &bins[0][0];                       // reuse smem: 1216 floats

    if (tid < NUM_CLS) fcnt[tid] = atomicExch(&g_counts[tid], 0.f);
    __syncthreads();
    for (int i = tid; i < NUM_CLS * NCH; i += BLOCK)
        cen[i] = atomicExch(&g_sums[i], 0.f) / fmaxf(fcnt[i >> 6], 1.f);
    __syncthreads();

    if (tid < NUM_CLS) {
        float s = 0.f;
#pragma unroll
        for (int c = 0; c < NCH; c++) {
            float v = cen[tid * NCH + c];
            s += v * v;
        }
        fnrm[tid] = fmaxf(sqrtf(s), 1e-8f);
    }
    __syncthreads();

    float acc = 0.f;
    if (tid < NUM_CLS * NUM_CLS) {
        int i = tid / NUM_CLS, j = tid % NUM_CLS;
        float d = 0.f;
#pragma unroll
        for (int c = 0; c < NCH; c++)
            d += cen[i * NCH + c] * cen[j * NCH + c];
        d /= (fnrm[i] * fnrm[j]);
        acc = (i == j) ? (1.f - d) : fmaxf(d, 0.f);
    }
#pragma unroll
    for (int o = 16; o > 0; o >>= 1)
        acc += __shfl_down_sync(0xffffffffu, acc, o);
    if (lane == 0) rbuf[warp] = acc;
    __syncthreads();
    if (warp == 0) {
        float v = (lane < WARPS) ? rbuf[lane] : 0.f;
#pragma unroll
        for (int o = 8; o > 0; o >>= 1)
            v += __shfl_down_sync(0xffffffffu, v, o);
        if (lane == 0) {
            out[0] = v / (float)(NUM_CLS * NUM_CLS * NUM_CLS);
            g_ticket = 0u;                          // reset for next replay
        }
    }
}

// ---------------------------------------------------------------------------
extern "C" void kernel_launch(void* const* d_in, const int* in_sizes, int n_in,
                              void* d_out, int out_size)
{
    const float* inputs  = (const float*)d_in[0];
    const int*   targets = (const int*)d_in[1];
    float*       out     = (float*)d_out;

    fused_kernel<<<NCHUNKS, BLOCK>>>(inputs, targets, out);
}

// round 13
// speedup vs baseline: 1.2153x; 1.2153x over previous
#include <cuda_runtime.h>
#include <cuda_bf16.h>
#include <cstddef>

#define NUM_CLS 19
#define NCH     64
#define HW      (512*512)
#define NBATCH  8
#define NPIX    (NBATCH*HW)          // 2,097,152 pixels
#define NBLK    (NBATCH*NCH)         // 512 blocks: one per (batch, channel)
#define BLOCK   512
#define WARPS   16

__device__ float         g_sums[NUM_CLS * NCH];
__device__ float         g_counts[NUM_CLS];
__device__ unsigned int  g_ticket;
__device__ unsigned char g_cls[NPIX];             // 2 MB label scratch (L2-resident)

// ---------------------------------------------------------------------------
// Kernel 1: compress labels int32 -> uint8 once, and count classes.
// ---------------------------------------------------------------------------
__global__ __launch_bounds__(512) void prep_kernel(const int* __restrict__ tgt)
{
    __shared__ int cnt[NUM_CLS];
    const int tid = threadIdx.x;
    if (tid < NUM_CLS) cnt[tid] = 0;
    __syncthreads();

    const int4* __restrict__ t4 = (const int4*)tgt;
    const int stride = gridDim.x * blockDim.x;
    for (int i = blockIdx.x * blockDim.x + tid; i < NPIX / 4; i += stride) {
        int4 v = t4[i];
        ((uchar4*)g_cls)[i] = make_uchar4((unsigned char)v.x, (unsigned char)v.y,
                                          (unsigned char)v.z, (unsigned char)v.w);
        atomicAdd(&cnt[v.x], 1); atomicAdd(&cnt[v.y], 1);
        atomicAdd(&cnt[v.z], 1); atomicAdd(&cnt[v.w], 1);
    }
    __syncthreads();
    if (tid < NUM_CLS) atomicAdd(&g_counts[tid], (float)cnt[tid]);
}

// ---------------------------------------------------------------------------
// Kernel 2: block = one (batch, channel) pair -> ONE contiguous 1 MB stream.
// ~3.5 streams per SM (vs 55 before) for DRAM row-buffer locality.
// bins[cls][tid] thread-private: no atomics, bank-conflict-free.
// Labels re-read from 2 MB g_cls -> L2 hits. Last block finalizes.
// ---------------------------------------------------------------------------
__global__ __launch_bounds__(BLOCK, 4) void accum_kernel(
    const float* __restrict__ in, float* __restrict__ out)
{
    __shared__ float bins[NUM_CLS][BLOCK];          // 38,912 B
    __shared__ float fcnt[NUM_CLS];
    __shared__ float fnrm[NUM_CLS];
    __shared__ float rbuf[WARPS];
    __shared__ int   sh_last;

    const int tid  = threadIdx.x;
    const int warp = tid >> 5;
    const int lane = tid & 31;
    const int blk  = blockIdx.x;                    // = b*NCH + c
    const int b    = blk >> 6;
    const int c    = blk & 63;

#pragma unroll
    for (int k = 0; k < NUM_CLS; k++) bins[k][tid] = 0.f;
    __syncthreads();

    const float4* __restrict__ src  = (const float4*)in + (size_t)blk * (HW / 4);
    const uchar4* __restrict__ cls4 = (const uchar4*)g_cls + (size_t)b * (HW / 4);

#pragma unroll 4
    for (int i = tid; i < HW / 4; i += BLOCK) {
        float4 x = __ldcs(src + i);
        uchar4 q = cls4[i];
        bins[q.x][tid] += x.x;
        bins[q.y][tid] += x.y;
        bins[q.z][tid] += x.z;
        bins[q.w][tid] += x.w;
    }
    __syncthreads();

    // One flush per block: warp-reduce each class, atomics into g_sums.
#pragma unroll
    for (int k = 0; k < NUM_CLS; k++) {
        float v = bins[k][tid];
#pragma unroll
        for (int o = 16; o > 0; o >>= 1)
            v += __shfl_down_sync(0xffffffffu, v, o);
        if (lane == 0) atomicAdd(&g_sums[k * NCH + c], v);
    }

    // Ticket: last block to arrive does the finalize.
    __threadfence();
    __syncthreads();
    if (tid == 0)
        sh_last = (atomicAdd(&g_ticket, 1u) == (unsigned)(NBLK - 1));
    __syncthreads();
    if (!sh_last) return;

    // ---------------- finalize (last block only) ----------------
    __threadfence();
    float* cen = &bins[0][0];                       // reuse smem: 1216 floats

    if (tid < NUM_CLS) fcnt[tid] = atomicExch(&g_counts[tid], 0.f);
    __syncthreads();
    for (int i = tid; i < NUM_CLS * NCH; i += BLOCK)
        cen[i] = atomicExch(&g_sums[i], 0.f) / fmaxf(fcnt[i >> 6], 1.f);
    __syncthreads();

    if (tid < NUM_CLS) {
        float s = 0.f;
#pragma unroll
        for (int ch = 0; ch < NCH; ch++) {
            float v = cen[tid * NCH + ch];
            s += v * v;
        }
        fnrm[tid] = fmaxf(sqrtf(s), 1e-8f);
    }
    __syncthreads();

    float acc = 0.f;
    if (tid < NUM_CLS * NUM_CLS) {
        int i = tid / NUM_CLS, j = tid % NUM_CLS;
        float d = 0.f;
#pragma unroll
        for (int ch = 0; ch < NCH; ch++)
            d += cen[i * NCH + ch] * cen[j * NCH + ch];
        d /= (fnrm[i] * fnrm[j]);
        acc = (i == j) ? (1.f - d) : fmaxf(d, 0.f);
    }
#pragma unroll
    for (int o = 16; o > 0; o >>= 1)
        acc += __shfl_down_sync(0xffffffffu, acc, o);
    if (lane == 0) rbuf[warp] = acc;
    __syncthreads();
    if (warp == 0) {
        float v = (lane < WARPS) ? rbuf[lane] : 0.f;
#pragma unroll
        for (int o = 8; o > 0; o >>= 1)
            v += __shfl_down_sync(0xffffffffu, v, o);
        if (lane == 0) {
            out[0] = v / (float)(NUM_CLS * NUM_CLS * NUM_CLS);
            g_ticket = 0u;                          // reset for next replay
        }
    }
}

// ---------------------------------------------------------------------------
extern "C" void kernel_launch(void* const* d_in, const int* in_sizes, int n_in,
                              void* d_out, int out_size)
{
    const float* inputs  = (const float*)d_in[0];
    const int*   targets = (const int*)d_in[1];
    float*       out     = (float*)d_out;

    prep_kernel<<<296, 512>>>(targets);
    accum_kernel<<<NBLK, BLOCK>>>(inputs, out);
}